// round 10
// baseline (speedup 1.0000x reference)
#include <cuda_runtime.h>
#include <cuda_fp16.h>
#include <cstdint>
#include <math.h>

// ---------------------------------------------------------------------------
// Problem constants
// ---------------------------------------------------------------------------
#define BB 2
#define TT 2048
#define EE 1024
#define HH 16
#define DD 64
#define MM (BB * TT)
#define BH (BB * HH)

// 0.125 (1/sqrt(64)) * log2(e): folded into Q so softmax uses exp2
#define SCALE_Q 0.18033688011112042f
#define ONES_H2 0x3C003C00u

// Scratch (device globals; allocation-free)
__device__ __half g_Xh[MM * EE];            // hidden fp16 [m][e]
__device__ __half g_Wth[3 * EE * EE];       // [mat][n=h*64+d][e] fp16
__device__ __half g_Woth[EE * EE];          // [n=e][k=h*64+d] fp16
__device__ __half g_Qh[BH * TT * DD];       // [bh][t][d] (pre-scaled by SCALE_Q)
__device__ __half g_Kh[BH * TT * DD];       // [bh][t][d]
__device__ __half g_Vh[BH * TT * DD];       // [bh][t][d]
__device__ __half g_attnh[MM * EE];         // gated attn out fp16 [m][h*64+d]

// ---------------------------------------------------------------------------
// Helpers
// ---------------------------------------------------------------------------
__device__ __forceinline__ uint32_t smem_u32(const void* p) {
    return (uint32_t)__cvta_generic_to_shared(p);
}
__device__ __forceinline__ void cp16(uint32_t dst, const void* src) {
    asm volatile("cp.async.cg.shared.global [%0], [%1], 16;\n" :: "r"(dst), "l"(src));
}
__device__ __forceinline__ void cp_commit() {
    asm volatile("cp.async.commit_group;\n" ::: "memory");
}
__device__ __forceinline__ void cp_wait1() {
    asm volatile("cp.async.wait_group 1;\n" ::: "memory");
}
__device__ __forceinline__ void cp_wait0() {
    asm volatile("cp.async.wait_group 0;\n" ::: "memory");
}
__device__ __forceinline__ void ldsm4(uint32_t addr, uint32_t& r0, uint32_t& r1,
                                      uint32_t& r2, uint32_t& r3) {
    asm volatile("ldmatrix.sync.aligned.m8n8.x4.shared.b16 {%0,%1,%2,%3}, [%4];"
                 : "=r"(r0), "=r"(r1), "=r"(r2), "=r"(r3) : "r"(addr));
}
__device__ __forceinline__ void ldsm4t(uint32_t addr, uint32_t& r0, uint32_t& r1,
                                       uint32_t& r2, uint32_t& r3) {
    asm volatile("ldmatrix.sync.aligned.m8n8.x4.trans.shared.b16 {%0,%1,%2,%3}, [%4];"
                 : "=r"(r0), "=r"(r1), "=r"(r2), "=r"(r3) : "r"(addr));
}
// m16n8k16 fp16 mma, fp32 accumulate
__device__ __forceinline__ void mma_f16(float* d, const uint32_t* a,
                                        uint32_t b0, uint32_t b1, const float* c) {
    asm volatile(
        "mma.sync.aligned.m16n8k16.row.col.f32.f16.f16.f32 "
        "{%0,%1,%2,%3}, {%4,%5,%6,%7}, {%8,%9}, {%10,%11,%12,%13};\n"
        : "=f"(d[0]), "=f"(d[1]), "=f"(d[2]), "=f"(d[3])
        : "r"(a[0]), "r"(a[1]), "r"(a[2]), "r"(a[3]),
          "r"(b0), "r"(b1),
          "f"(c[0]), "f"(c[1]), "f"(c[2]), "f"(c[3]));
}
__device__ __forceinline__ uint32_t packh2(float lo, float hi) {
    __half2 h = __floats2half2_rn(lo, hi);
    return *reinterpret_cast<uint32_t*>(&h);
}
// 2^x on a packed half2 built from two floats
__device__ __forceinline__ uint32_t exp2h2(float lo, float hi) {
    __half2 h = h2exp2(__floats2half2_rn(lo, hi));
    return *reinterpret_cast<uint32_t*>(&h);
}

// ---------------------------------------------------------------------------
// Conversion kernels
// ---------------------------------------------------------------------------
__global__ void cvt_x(const float* __restrict__ src, __half* __restrict__ dst)
{
    const int f = blockIdx.x * 256 + threadIdx.x;   // float4 index
    float4 v = *reinterpret_cast<const float4*>(src + (size_t)f * 4);
    uint2 o;
    o.x = packh2(v.x, v.y);
    o.y = packh2(v.z, v.w);
    *reinterpret_cast<uint2*>(dst + (size_t)f * 4) = o;
}

// src fp32 [batch][R][C] -> dst fp16 [batch][C][R]
__global__ void cvt_transpose(const float* __restrict__ src, __half* __restrict__ dst,
                              int R, int C)
{
    __shared__ float tile[32][33];
    const int c0 = blockIdx.x * 32;
    const int r0 = blockIdx.y * 32;
    const size_t boff = (size_t)blockIdx.z * R * C;
#pragma unroll
    for (int i = 0; i < 4; i++) {
        const int r = r0 + threadIdx.y + i * 8;
        tile[threadIdx.y + i * 8][threadIdx.x] = src[boff + (size_t)r * C + c0 + threadIdx.x];
    }
    __syncthreads();
#pragma unroll
    for (int i = 0; i < 4; i++) {
        const int c = c0 + threadIdx.y + i * 8;
        dst[boff + (size_t)c * R + r0 + threadIdx.x] =
            __float2half_rn(tile[threadIdx.x][threadIdx.y + i * 8]);
    }
}

// Fused QKV weight transpose: z in [0,48), mat = z>>4, h = z&15.
__global__ void cvt_transpose_qkv(const float* __restrict__ Wq,
                                  const float* __restrict__ Wk,
                                  const float* __restrict__ Wv,
                                  __half* __restrict__ dst)
{
    __shared__ float tile[32][33];
    const int z   = blockIdx.z;
    const int mat = z >> 4;
    const int h   = z & 15;
    const float* src = (mat == 0 ? Wq : (mat == 1 ? Wk : Wv)) + (size_t)h * EE * DD;
    __half* d = dst + (size_t)mat * EE * EE + (size_t)h * DD * EE;

    const int c0 = blockIdx.x * 32;   // D
    const int r0 = blockIdx.y * 32;   // E
#pragma unroll
    for (int i = 0; i < 4; i++) {
        const int r = r0 + threadIdx.y + i * 8;
        tile[threadIdx.y + i * 8][threadIdx.x] = src[(size_t)r * DD + c0 + threadIdx.x];
    }
    __syncthreads();
#pragma unroll
    for (int i = 0; i < 4; i++) {
        const int c = c0 + threadIdx.y + i * 8;
        d[(size_t)c * EE + r0 + threadIdx.x] =
            __float2half_rn(tile[threadIdx.x][threadIdx.y + i * 8]);
    }
}

// ---------------------------------------------------------------------------
// GEMM: CTA tile 128(M) x 256(N), 8 warps, warp tile 64x64. BK = 64 halves.
// Smem: 3 stages of (A 128x72h = 18432 B, B 256x72h = 36864 B) = 55296 B/stage.
// Total 165888 B -> 1 CTA/SM (reg-bound anyway). Epilogues overlay stages.
// ---------------------------------------------------------------------------
#define AH_LD 72              // halves per row (144 B)
#define GSTAGE 55296
#define GBOFF 18432           // B offset within stage
#define GEMM_SMEM (3 * GSTAGE)
#define CH_LD 264             // halves, qkv epilogue (128x264x2 = 67584 B)
#define CF_LD 264             // floats, out epilogue (128x264x4 = 135168 B)

// ---------------------------------------------------------------------------
// Kernel 1: fused QKV projection. grid (12, 32): n0 = bx*256 (one mat, 4 heads).
// ---------------------------------------------------------------------------
__global__ __launch_bounds__(256) void qkv_gemm_h(
    const float* __restrict__ bq, const float* __restrict__ bk,
    const float* __restrict__ bv)
{
    extern __shared__ char smc[];
    const uint32_t smb = smem_u32(smc);
    __shared__ float sbias[256];

    const int n0   = blockIdx.x * 256;
    const int m0   = blockIdx.y * 128;
    const int mat  = n0 >> 10;
    const int nloc = n0 & 1023;

    const __half* Wt  = g_Wth + (size_t)mat * EE * EE;
    const float* bias = (mat == 0 ? bq : (mat == 1 ? bk : bv));
    __half* dst       = (mat == 0 ? g_Qh : (mat == 1 ? g_Kh : g_Vh));
    const float qscale = (mat == 0) ? SCALE_Q : 1.0f;

    const int tid  = threadIdx.x;
    const int wid  = tid >> 5;
    const int lane = tid & 31;
    const int gr   = lane >> 2;
    const int tg   = lane & 3;
    const int wm   = (wid & 1) * 64;     // warp m offset
    const int wn   = (wid >> 1) * 64;    // warp n offset
    const int lrow = lane & 15;
    const int lcol = (lane >> 4) * 16;   // byte offset

    sbias[tid] = bias[nloc + tid];

    auto issue = [&](int kt) {
        const int k0 = kt * 64;          // halves
        const uint32_t Au = smb + (kt % 3) * GSTAGE;
        const uint32_t Bu = Au + GBOFF;
        // A: 128 rows x 64 halves = 1024 16B chunks
#pragma unroll
        for (int i = 0; i < 4; i++) {
            const int ch = tid + i * 256;
            const int r = ch >> 3, c = ch & 7;
            cp16(Au + r * (AH_LD * 2) + c * 16, g_Xh + (size_t)(m0 + r) * EE + k0 + c * 8);
        }
        // B: 256 rows x 64 halves = 2048 chunks
#pragma unroll
        for (int i = 0; i < 8; i++) {
            const int ch = tid + i * 256;
            const int r = ch >> 3, c = ch & 7;
            cp16(Bu + r * (AH_LD * 2) + c * 16, Wt + (size_t)(nloc + r) * EE + k0 + c * 8);
        }
        cp_commit();
    };

    float acc[4][8][4];
#pragma unroll
    for (int i = 0; i < 4; i++)
#pragma unroll
        for (int j = 0; j < 8; j++)
#pragma unroll
            for (int k = 0; k < 4; k++) acc[i][j][k] = 0.f;

    issue(0);
    issue(1);

    for (int kt = 0; kt < 16; kt++) {
        if (kt == 15) cp_wait0(); else cp_wait1();
        __syncthreads();
        if (kt + 2 < 16) issue(kt + 2);

        const uint32_t Au = smb + (kt % 3) * GSTAGE;
        const uint32_t aoffA = Au + (wm + lrow) * (AH_LD * 2) + lcol;
        const uint32_t aoffB = Au + GBOFF + (wn + lrow) * (AH_LD * 2) + lcol;

#pragma unroll
        for (int kc = 0; kc < 4; kc++) {
            uint32_t a[4][4];
#pragma unroll
            for (int ii = 0; ii < 4; ii++)
                ldsm4(aoffA + ii * 16 * (AH_LD * 2) + kc * 32,
                      a[ii][0], a[ii][1], a[ii][2], a[ii][3]);
#pragma unroll
            for (int jn = 0; jn < 4; jn++) {
                uint32_t b[4];
                ldsm4(aoffB + jn * 16 * (AH_LD * 2) + kc * 32, b[0], b[1], b[2], b[3]);
#pragma unroll
                for (int ii = 0; ii < 4; ii++) {
                    mma_f16(acc[ii][jn * 2],     a[ii], b[0], b[2], acc[ii][jn * 2]);
                    mma_f16(acc[ii][jn * 2 + 1], a[ii], b[1], b[3], acc[ii][jn * 2 + 1]);
                }
            }
        }
    }

    __syncthreads();
    __half* Csh = reinterpret_cast<__half*>(smc);
#pragma unroll
    for (int ii = 0; ii < 4; ii++)
#pragma unroll
        for (int n8 = 0; n8 < 8; n8++) {
            const int row = wm + ii * 16 + gr;
            const int col = wn + n8 * 8 + 2 * tg;
            const float b0 = sbias[col], b1 = sbias[col + 1];
            *reinterpret_cast<uint32_t*>(Csh + row * CH_LD + col) =
                packh2((acc[ii][n8][0] + b0) * qscale, (acc[ii][n8][1] + b1) * qscale);
            *reinterpret_cast<uint32_t*>(Csh + (row + 8) * CH_LD + col) =
                packh2((acc[ii][n8][2] + b0) * qscale, (acc[ii][n8][3] + b1) * qscale);
        }
    __syncthreads();

    // Write out 128 rows x 256 halves = 4096 8-half chunks (16 per thread).
    const int bb = m0 >> 11;
#pragma unroll
    for (int i = 0; i < 16; i++) {
        const int f = tid + i * 256;       // 0..4095
        const int r = f >> 5;              // 0..127
        const int c8 = (f & 31) * 8;       // 0..248
        const int t = (m0 & (TT - 1)) + r;
        const int n = nloc + c8;
        const int h = n >> 6, d = n & 63;
        uint4 v = *reinterpret_cast<const uint4*>(Csh + r * CH_LD + c8);
        *reinterpret_cast<uint4*>(dst + ((size_t)((bb * HH + h) * TT + t)) * DD + d) = v;
    }
}

// ---------------------------------------------------------------------------
// Kernel 3: output projection. grid (4, 32) = 128 CTAs (single wave).
// ---------------------------------------------------------------------------
__global__ __launch_bounds__(256) void out_gemm_h(
    const float* __restrict__ bo, const float* __restrict__ gate,
    float* __restrict__ out)
{
    extern __shared__ char smc[];
    const uint32_t smb = smem_u32(smc);
    __shared__ float gbias[256];

    const int n0 = blockIdx.x * 256;
    const int m0 = blockIdx.y * 128;

    const int tid  = threadIdx.x;
    const int wid  = tid >> 5;
    const int lane = tid & 31;
    const int gr   = lane >> 2;
    const int tg   = lane & 3;
    const int wm   = (wid & 1) * 64;
    const int wn   = (wid >> 1) * 64;
    const int lrow = lane & 15;
    const int lcol = (lane >> 4) * 16;

    {
        float s = 0.f;
#pragma unroll
        for (int hh = 0; hh < HH; hh++)
            s = fmaf(gate[hh], bo[(size_t)hh * EE + n0 + tid], s);
        gbias[tid] = s;
    }

    auto issue = [&](int kt) {
        const int k0 = kt * 64;
        const uint32_t Au = smb + (kt % 3) * GSTAGE;
        const uint32_t Bu = Au + GBOFF;
#pragma unroll
        for (int i = 0; i < 4; i++) {
            const int ch = tid + i * 256;
            const int r = ch >> 3, c = ch & 7;
            cp16(Au + r * (AH_LD * 2) + c * 16, g_attnh + (size_t)(m0 + r) * EE + k0 + c * 8);
        }
#pragma unroll
        for (int i = 0; i < 8; i++) {
            const int ch = tid + i * 256;
            const int r = ch >> 3, c = ch & 7;
            cp16(Bu + r * (AH_LD * 2) + c * 16, g_Woth + (size_t)(n0 + r) * EE + k0 + c * 8);
        }
        cp_commit();
    };

    float acc[4][8][4];
#pragma unroll
    for (int i = 0; i < 4; i++)
#pragma unroll
        for (int j = 0; j < 8; j++)
#pragma unroll
            for (int k = 0; k < 4; k++) acc[i][j][k] = 0.f;

    issue(0);
    issue(1);

    for (int kt = 0; kt < 16; kt++) {
        if (kt == 15) cp_wait0(); else cp_wait1();
        __syncthreads();
        if (kt + 2 < 16) issue(kt + 2);

        const uint32_t Au = smb + (kt % 3) * GSTAGE;
        const uint32_t aoffA = Au + (wm + lrow) * (AH_LD * 2) + lcol;
        const uint32_t aoffB = Au + GBOFF + (wn + lrow) * (AH_LD * 2) + lcol;

#pragma unroll
        for (int kc = 0; kc < 4; kc++) {
            uint32_t a[4][4];
#pragma unroll
            for (int ii = 0; ii < 4; ii++)
                ldsm4(aoffA + ii * 16 * (AH_LD * 2) + kc * 32,
                      a[ii][0], a[ii][1], a[ii][2], a[ii][3]);
#pragma unroll
            for (int jn = 0; jn < 4; jn++) {
                uint32_t b[4];
                ldsm4(aoffB + jn * 16 * (AH_LD * 2) + kc * 32, b[0], b[1], b[2], b[3]);
#pragma unroll
                for (int ii = 0; ii < 4; ii++) {
                    mma_f16(acc[ii][jn * 2],     a[ii], b[0], b[2], acc[ii][jn * 2]);
                    mma_f16(acc[ii][jn * 2 + 1], a[ii], b[1], b[3], acc[ii][jn * 2 + 1]);
                }
            }
        }
    }

    __syncthreads();
    float* Cs = reinterpret_cast<float*>(smc);
#pragma unroll
    for (int ii = 0; ii < 4; ii++)
#pragma unroll
        for (int n8 = 0; n8 < 8; n8++) {
            const int row = wm + ii * 16 + gr;
            const int col = wn + n8 * 8 + 2 * tg;
            *reinterpret_cast<float2*>(Cs + row * CF_LD + col) =
                make_float2(acc[ii][n8][0], acc[ii][n8][1]);
            *reinterpret_cast<float2*>(Cs + (row + 8) * CF_LD + col) =
                make_float2(acc[ii][n8][2], acc[ii][n8][3]);
        }
    __syncthreads();

#pragma unroll
    for (int i = 0; i < 32; i++) {
        const int f = tid + i * 256;       // 0..8191 float4 chunks
        const int r = f >> 6;
        const int c4 = (f & 63) * 4;
        float4 v = *reinterpret_cast<const float4*>(Cs + r * CF_LD + c4);
        v.x += gbias[c4 + 0];
        v.y += gbias[c4 + 1];
        v.z += gbias[c4 + 2];
        v.w += gbias[c4 + 3];
        *reinterpret_cast<float4*>(out + (size_t)(m0 + r) * EE + n0 + c4) = v;
    }
}

// ---------------------------------------------------------------------------
// Kernel 2: FA2 flash attention, fp16 MMA (unchanged from R8).
// ---------------------------------------------------------------------------
#define KH_LD 72
#define KTILE_BYTES (64 * KH_LD * 2)   // 9216
#define ATTN_STAGE (2 * KTILE_BYTES)   // 18432
#define QTILE_BYTES (128 * KH_LD * 2)  // 18432
#define ATTN_SMEM (QTILE_BYTES + 3 * ATTN_STAGE)  // 73728

__global__ __launch_bounds__(256, 2) void flash_attn_h(const float* __restrict__ gate)
{
    extern __shared__ char smc[];
    const uint32_t smb = smem_u32(smc);
    const uint32_t Qu  = smb;
    const uint32_t St0 = smb + QTILE_BYTES;

    const int bh = blockIdx.y;
    const int q0 = blockIdx.x * 128;
    const int tid  = threadIdx.x;
    const int wid  = tid >> 5;
    const int lane = tid & 31;
    const int gr   = lane >> 2;
    const int tg   = lane & 3;
    const int wrow = wid * 16;
    const int lrow = lane & 15;
    const int lcol = (lane >> 4) * 16;

    const __half* Qg = g_Qh + ((size_t)bh * TT + q0) * DD;
    const __half* Kg = g_Kh + (size_t)bh * TT * DD;
    const __half* Vg = g_Vh + (size_t)bh * TT * DD;

    auto issueKV = [&](int kb) {
        const uint32_t Ku = St0 + (kb % 3) * ATTN_STAGE;
        const uint32_t Vu = Ku + KTILE_BYTES;
        const __half* Ksrc = Kg + (size_t)(kb * 64) * DD;
        const __half* Vsrc = Vg + (size_t)(kb * 64) * DD;
#pragma unroll
        for (int i = 0; i < 2; i++) {
            const int ch = tid + i * 256;     // 0..511
            const int r = ch >> 3, c = ch & 7;
            cp16(Ku + r * (KH_LD * 2) + c * 16, Ksrc + (size_t)r * DD + c * 8);
        }
#pragma unroll
        for (int i = 0; i < 2; i++) {
            const int ch = tid + i * 256;
            const int r = ch >> 3, c = ch & 7;
            cp16(Vu + r * (KH_LD * 2) + c * 16, Vsrc + (size_t)r * DD + c * 8);
        }
        cp_commit();
    };

    // Group 0 = Q tile + K/V tile 0
    {
#pragma unroll
        for (int i = 0; i < 4; i++) {
            const int ch = tid + i * 256;     // 0..1023
            const int r = ch >> 3, c = ch & 7;
            cp16(Qu + r * (KH_LD * 2) + c * 16, Qg + (size_t)r * DD + c * 8);
        }
        issueKV(0);   // commits group 0 (Q + KV0)
    }
    issueKV(1);       // group 1

    cp_wait1();       // Q + KV0 complete
    __syncthreads();

    // Q A-fragments: 4 k-chunks (d 0..63)
    uint32_t qa[4][4];
    {
        const uint32_t qoff = Qu + (wrow + lrow) * (KH_LD * 2) + lcol;
#pragma unroll
        for (int kc = 0; kc < 4; kc++)
            ldsm4(qoff + kc * 32, qa[kc][0], qa[kc][1], qa[kc][2], qa[kc][3]);
    }

    float oc[8][4];
    float lc[4];      // ones-column accumulator: lc[0]=row gr sum, lc[2]=row gr+8
#pragma unroll
    for (int j = 0; j < 8; j++)
#pragma unroll
        for (int k = 0; k < 4; k++) oc[j][k] = 0.f;
#pragma unroll
    for (int k = 0; k < 4; k++) lc[k] = 0.f;
    float m0 = -1e30f, m1 = -1e30f;

    for (int kb = 0; kb < TT / 64; kb++) {
        if (kb == TT / 64 - 1) cp_wait0(); else cp_wait1();
        __syncthreads();
        if (kb + 2 < TT / 64) issueKV(kb + 2);

        const uint32_t Ku = St0 + (kb % 3) * ATTN_STAGE;
        const uint32_t koff = Ku + lrow * (KH_LD * 2) + lcol;
        const uint32_t voff = Ku + KTILE_BYTES + lrow * (KH_LD * 2) + lcol;

        // ---- S = Q K^T (16 x 64 per warp), log2-domain scores ----
        float sc[8][4];
#pragma unroll
        for (int j = 0; j < 8; j++)
#pragma unroll
            for (int k = 0; k < 4; k++) sc[j][k] = 0.f;

#pragma unroll
        for (int kc = 0; kc < 4; kc++) {
#pragma unroll
            for (int jp = 0; jp < 4; jp++) {
                uint32_t b[4];
                ldsm4(koff + jp * 16 * (KH_LD * 2) + kc * 32, b[0], b[1], b[2], b[3]);
                mma_f16(sc[jp * 2],     qa[kc], b[0], b[2], sc[jp * 2]);
                mma_f16(sc[jp * 2 + 1], qa[kc], b[1], b[3], sc[jp * 2 + 1]);
            }
        }

        // ---- Online softmax (base-2): max via shuffles ----
        float mx0 = -1e30f, mx1 = -1e30f;
#pragma unroll
        for (int j = 0; j < 8; j++) {
            mx0 = fmaxf(mx0, fmaxf(sc[j][0], sc[j][1]));
            mx1 = fmaxf(mx1, fmaxf(sc[j][2], sc[j][3]));
        }
        mx0 = fmaxf(mx0, __shfl_xor_sync(0xffffffffu, mx0, 1));
        mx0 = fmaxf(mx0, __shfl_xor_sync(0xffffffffu, mx0, 2));
        mx1 = fmaxf(mx1, __shfl_xor_sync(0xffffffffu, mx1, 1));
        mx1 = fmaxf(mx1, __shfl_xor_sync(0xffffffffu, mx1, 2));

        const float mn0 = fmaxf(m0, mx0);
        const float mn1 = fmaxf(m1, mx1);
        float al0, al1;
        asm("ex2.approx.f32 %0, %1;" : "=f"(al0) : "f"(m0 - mn0));
        asm("ex2.approx.f32 %0, %1;" : "=f"(al1) : "f"(m1 - mn1));
        m0 = mn0;
        m1 = mn1;

        // Rescale O and l accumulators
#pragma unroll
        for (int j = 0; j < 8; j++) {
            oc[j][0] *= al0;
            oc[j][1] *= al0;
            oc[j][2] *= al1;
            oc[j][3] *= al1;
        }
        lc[0] *= al0; lc[1] *= al0; lc[2] *= al1; lc[3] *= al1;

        // ---- P = 2^(S - mn) directly in fp16 A-frag layout ----
        uint32_t pa[4][4];
#pragma unroll
        for (int kc = 0; kc < 4; kc++) {
            pa[kc][0] = exp2h2(sc[2 * kc][0] - mn0,     sc[2 * kc][1] - mn0);
            pa[kc][1] = exp2h2(sc[2 * kc][2] - mn1,     sc[2 * kc][3] - mn1);
            pa[kc][2] = exp2h2(sc[2 * kc + 1][0] - mn0, sc[2 * kc + 1][1] - mn0);
            pa[kc][3] = exp2h2(sc[2 * kc + 1][2] - mn1, sc[2 * kc + 1][3] - mn1);
        }

        // ---- O += P V ; l += P * ones (row-sum via MMA, no shuffles) ----
#pragma unroll
        for (int kc = 0; kc < 4; kc++) {
            mma_f16(lc, pa[kc], ONES_H2, ONES_H2, lc);
#pragma unroll
            for (int jp = 0; jp < 4; jp++) {
                uint32_t b[4];
                ldsm4t(voff + kc * 16 * (KH_LD * 2) + jp * 32, b[0], b[1], b[2], b[3]);
                mma_f16(oc[jp * 2],     pa[kc], b[0], b[1], oc[jp * 2]);
                mma_f16(oc[jp * 2 + 1], pa[kc], b[2], b[3], oc[jp * 2 + 1]);
            }
        }
    }

    // ---- Epilogue: normalize, apply gate, write fp16 g_attnh ----
    const int b  = bh >> 4;
    const int h  = bh & 15;
    const float g = gate[h];
    const float inv0 = g / lc[0];
    const float inv1 = g / lc[2];
    const int r0 = q0 + wrow + gr;
    __half* row0 = g_attnh + ((size_t)(b * TT + r0)) * EE + h * DD;
    __half* row1 = g_attnh + ((size_t)(b * TT + r0 + 8)) * EE + h * DD;
#pragma unroll
    for (int j = 0; j < 8; j++) {
        const int col = j * 8 + 2 * tg;
        *reinterpret_cast<uint32_t*>(row0 + col) = packh2(oc[j][0] * inv0, oc[j][1] * inv0);
        *reinterpret_cast<uint32_t*>(row1 + col) = packh2(oc[j][2] * inv1, oc[j][3] * inv1);
    }
}

// ---------------------------------------------------------------------------
extern "C" void kernel_launch(void* const* d_in, const int* in_sizes, int n_in,
                              void* d_out, int out_size)
{
    const float* X    = (const float*)d_in[0];
    const float* Wq   = (const float*)d_in[1];
    const float* bq   = (const float*)d_in[2];
    const float* Wk   = (const float*)d_in[3];
    const float* bk   = (const float*)d_in[4];
    const float* Wv   = (const float*)d_in[5];
    const float* bv   = (const float*)d_in[6];
    const float* Wo   = (const float*)d_in[7];
    const float* bo   = (const float*)d_in[8];
    const float* gate = (const float*)d_in[9];
    float* out = (float*)d_out;

    __half* Xh;
    __half* Wth;
    __half* Woth;
    cudaGetSymbolAddress((void**)&Xh,   g_Xh);
    cudaGetSymbolAddress((void**)&Wth,  g_Wth);
    cudaGetSymbolAddress((void**)&Woth, g_Woth);

    cudaFuncSetAttribute(qkv_gemm_h,   cudaFuncAttributeMaxDynamicSharedMemorySize, GEMM_SMEM);
    cudaFuncSetAttribute(out_gemm_h,   cudaFuncAttributeMaxDynamicSharedMemorySize, GEMM_SMEM);
    cudaFuncSetAttribute(flash_attn_h, cudaFuncAttributeMaxDynamicSharedMemorySize, ATTN_SMEM);

    // 0) Conversions: X -> fp16; weights -> fp16 transposed (fused QKV)
    cvt_x<<<(MM * EE) / 1024, 256>>>(X, Xh);
    cvt_transpose_qkv<<<dim3(DD / 32, EE / 32, 48), dim3(32, 8)>>>(Wq, Wk, Wv, Wth);
    cvt_transpose<<<dim3(EE / 32, EE / 32, 1), dim3(32, 8)>>>(Wo, Woth, EE, EE);

    // 1) QKV projection (fp16 MMA, 128x256 CTA tile)
    qkv_gemm_h<<<dim3(3072 / 256, MM / 128), 256, GEMM_SMEM>>>(bq, bk, bv);
    // 2) Flash attention (fp16 MMA)
    flash_attn_h<<<dim3(TT / 128, BH), 256, ATTN_SMEM>>>(gate);
    // 3) Output projection (fp16 MMA, 128x256 CTA tile, single wave)
    out_gemm_h<<<dim3(EE / 256, MM / 128), 256, GEMM_SMEM>>>(bo, gate, out);
}

// round 12
// speedup vs baseline: 1.0461x; 1.0461x over previous
#include <cuda_runtime.h>
#include <cuda_fp16.h>
#include <cstdint>
#include <math.h>

// ---------------------------------------------------------------------------
// Problem constants
// ---------------------------------------------------------------------------
#define BB 2
#define TT 2048
#define EE 1024
#define HH 16
#define DD 64
#define MM (BB * TT)
#define BH (BB * HH)

// 0.125 (1/sqrt(64)) * log2(e): folded into Q so softmax uses exp2
#define SCALE_Q 0.18033688011112042f
#define ONES_H2 0x3C003C00u

// Scratch (device globals; allocation-free)
__device__ __half g_Xh[MM * EE];            // hidden fp16 [m][e]
__device__ __half g_Wth[3 * EE * EE];       // [mat][n=h*64+d][e] fp16
__device__ __half g_Woth[EE * EE];          // [n=e][k=h*64+d] fp16
__device__ __half g_Qh[BH * TT * DD];       // [bh][t][d] (pre-scaled by SCALE_Q)
__device__ __half g_Kh[BH * TT * DD];       // [bh][t][d]
__device__ __half g_Vh[BH * TT * DD];       // [bh][t][d]
__device__ __half g_attnh[MM * EE];         // gated attn out fp16 [m][h*64+d]

// ---------------------------------------------------------------------------
// Helpers
// ---------------------------------------------------------------------------
__device__ __forceinline__ uint32_t smem_u32(const void* p) {
    return (uint32_t)__cvta_generic_to_shared(p);
}
__device__ __forceinline__ void cp16(uint32_t dst, const void* src) {
    asm volatile("cp.async.cg.shared.global [%0], [%1], 16;\n" :: "r"(dst), "l"(src));
}
__device__ __forceinline__ void cp_commit() {
    asm volatile("cp.async.commit_group;\n" ::: "memory");
}
__device__ __forceinline__ void cp_wait0() {
    asm volatile("cp.async.wait_group 0;\n" ::: "memory");
}
__device__ __forceinline__ void cp_wait1() {
    asm volatile("cp.async.wait_group 1;\n" ::: "memory");
}
__device__ __forceinline__ void cp_wait2() {
    asm volatile("cp.async.wait_group 2;\n" ::: "memory");
}
__device__ __forceinline__ void ldsm4(uint32_t addr, uint32_t& r0, uint32_t& r1,
                                      uint32_t& r2, uint32_t& r3) {
    asm volatile("ldmatrix.sync.aligned.m8n8.x4.shared.b16 {%0,%1,%2,%3}, [%4];"
                 : "=r"(r0), "=r"(r1), "=r"(r2), "=r"(r3) : "r"(addr));
}
__device__ __forceinline__ void ldsm4t(uint32_t addr, uint32_t& r0, uint32_t& r1,
                                       uint32_t& r2, uint32_t& r3) {
    asm volatile("ldmatrix.sync.aligned.m8n8.x4.trans.shared.b16 {%0,%1,%2,%3}, [%4];"
                 : "=r"(r0), "=r"(r1), "=r"(r2), "=r"(r3) : "r"(addr));
}
// m16n8k16 fp16 mma, fp32 accumulate
__device__ __forceinline__ void mma_f16(float* d, const uint32_t* a,
                                        uint32_t b0, uint32_t b1, const float* c) {
    asm volatile(
        "mma.sync.aligned.m16n8k16.row.col.f32.f16.f16.f32 "
        "{%0,%1,%2,%3}, {%4,%5,%6,%7}, {%8,%9}, {%10,%11,%12,%13};\n"
        : "=f"(d[0]), "=f"(d[1]), "=f"(d[2]), "=f"(d[3])
        : "r"(a[0]), "r"(a[1]), "r"(a[2]), "r"(a[3]),
          "r"(b0), "r"(b1),
          "f"(c[0]), "f"(c[1]), "f"(c[2]), "f"(c[3]));
}
__device__ __forceinline__ uint32_t packh2(float lo, float hi) {
    __half2 h = __floats2half2_rn(lo, hi);
    return *reinterpret_cast<uint32_t*>(&h);
}
// 2^x on a packed half2 built from two floats
__device__ __forceinline__ uint32_t exp2h2(float lo, float hi) {
    __half2 h = h2exp2(__floats2half2_rn(lo, hi));
    return *reinterpret_cast<uint32_t*>(&h);
}

// ---------------------------------------------------------------------------
// Kernel 0: ALL conversions fused into one launch.
//   blocks [0, 4096)       : X fp32 -> fp16
//   blocks [4096, 7168)    : Wq/Wk/Wv -> transposed fp16
//   blocks [7168, 8192)    : Wo -> transposed fp16
// ---------------------------------------------------------------------------
__global__ __launch_bounds__(256) void cvt_all(
    const float* __restrict__ X,
    const float* __restrict__ Wq, const float* __restrict__ Wk,
    const float* __restrict__ Wv, const float* __restrict__ Wo,
    __half* __restrict__ Xh, __half* __restrict__ Wth,
    __half* __restrict__ Woth)
{
    const int bid = blockIdx.x;
    const int tid = threadIdx.x;

    if (bid < 4096) {
        const int f = bid * 256 + tid;   // float4 index
        float4 v = *reinterpret_cast<const float4*>(X + (size_t)f * 4);
        uint2 o;
        o.x = packh2(v.x, v.y);
        o.y = packh2(v.z, v.w);
        *reinterpret_cast<uint2*>(Xh + (size_t)f * 4) = o;
        return;
    }

    __shared__ float tile[32][33];
    const int tx = tid & 31;
    const int ty = tid >> 5;   // 0..7

    if (bid < 7168) {
        // QKV weight transpose: [E][D] fp32 -> [d][e] fp16
        const int idx = bid - 4096;
        const int z   = idx >> 6;        // 0..47
        const int rem = idx & 63;
        const int mat = z >> 4;
        const int h   = z & 15;
        const int c0  = (rem & 1) * 32;  // D
        const int r0  = (rem >> 1) * 32; // E
        const float* src = (mat == 0 ? Wq : (mat == 1 ? Wk : Wv)) + (size_t)h * EE * DD;
        __half* d = Wth + (size_t)mat * EE * EE + (size_t)h * DD * EE;
#pragma unroll
        for (int i = 0; i < 4; i++) {
            const int r = r0 + ty + i * 8;
            tile[ty + i * 8][tx] = src[(size_t)r * DD + c0 + tx];
        }
        __syncthreads();
#pragma unroll
        for (int i = 0; i < 4; i++) {
            const int c = c0 + ty + i * 8;
            d[(size_t)c * EE + r0 + tx] = __float2half_rn(tile[tx][ty + i * 8]);
        }
    } else {
        // Wo transpose: [H*D][E] fp32 -> [e][k] fp16
        const int idx = bid - 7168;
        const int c0  = (idx & 31) * 32;  // E (cols of src)
        const int r0  = (idx >> 5) * 32;  // H*D (rows of src)
#pragma unroll
        for (int i = 0; i < 4; i++) {
            const int r = r0 + ty + i * 8;
            tile[ty + i * 8][tx] = Wo[(size_t)r * EE + c0 + tx];
        }
        __syncthreads();
#pragma unroll
        for (int i = 0; i < 4; i++) {
            const int c = c0 + ty + i * 8;
            Woth[(size_t)c * EE + r0 + tx] = __float2half_rn(tile[tx][ty + i * 8]);
        }
    }
}

// ---------------------------------------------------------------------------
// GEMM (exact R8 geometry): CTA tile 128x128, 8 warps, warp tile 32x64.
// BK = 64 halves -> 16 mainloop iterations. 3 stages of
// (A 128x72h = 18432 B, B 128x72h = 18432 B) = 36864 B/stage, 110592 total,
// 2 CTAs/SM. Epilogues overlay stage memory.
// ---------------------------------------------------------------------------
#define AH_LD 72          // halves (144 B row)
#define STAGE_BYTES 36864
#define BOFF 18432
#define GEMM_SMEM (3 * STAGE_BYTES)
#define CH_LD 136         // halves (qkv epilogue)
#define CF_LD 132         // floats (out epilogue)

// ---------------------------------------------------------------------------
// Kernel 1: fused QKV projection, fp16 MMA. grid (24, 32).
// ---------------------------------------------------------------------------
__global__ __launch_bounds__(256, 2) void qkv_gemm_h(
    const float* __restrict__ bq, const float* __restrict__ bk,
    const float* __restrict__ bv)
{
    extern __shared__ char smc[];
    const uint32_t smb = smem_u32(smc);
    __shared__ float sbias[128];

    const int n0   = blockIdx.x * 128;
    const int m0   = blockIdx.y * 128;
    const int mat  = n0 >> 10;
    const int nloc = n0 & 1023;

    const __half* Wt  = g_Wth + (size_t)mat * EE * EE;
    const float* bias = (mat == 0 ? bq : (mat == 1 ? bk : bv));
    __half* dst       = (mat == 0 ? g_Qh : (mat == 1 ? g_Kh : g_Vh));
    const float qscale = (mat == 0) ? SCALE_Q : 1.0f;

    const int tid  = threadIdx.x;
    const int wid  = tid >> 5;
    const int lane = tid & 31;
    const int gr   = lane >> 2;
    const int tg   = lane & 3;
    const int wrow = (wid & 3) * 32;
    const int wcol = (wid >> 2) * 64;
    const int lrow = lane & 15;
    const int lcol = (lane >> 4) * 16;   // byte offset

    if (tid < 128) sbias[tid] = bias[nloc + tid];

    auto issue = [&](int kt) {
        const int k0 = kt * 64;          // halves
        const uint32_t Au = smb + (kt % 3) * STAGE_BYTES;
        const uint32_t Bu = Au + BOFF;
#pragma unroll
        for (int i = 0; i < 4; i++) {
            const int ch = tid + i * 256;       // 0..1023
            const int r = ch >> 3, c = ch & 7;
            cp16(Au + r * (AH_LD * 2) + c * 16, g_Xh + (size_t)(m0 + r) * EE + k0 + c * 8);
        }
#pragma unroll
        for (int i = 0; i < 4; i++) {
            const int ch = tid + i * 256;
            const int r = ch >> 3, c = ch & 7;
            cp16(Bu + r * (AH_LD * 2) + c * 16, Wt + (size_t)(nloc + r) * EE + k0 + c * 8);
        }
        cp_commit();
    };

    float acc[2][8][4];
#pragma unroll
    for (int i = 0; i < 2; i++)
#pragma unroll
        for (int j = 0; j < 8; j++)
#pragma unroll
            for (int k = 0; k < 4; k++) acc[i][j][k] = 0.f;

    issue(0);
    issue(1);

    for (int kt = 0; kt < 16; kt++) {
        if (kt == 15) cp_wait0(); else cp_wait1();
        __syncthreads();
        if (kt + 2 < 16) issue(kt + 2);

        const uint32_t Au = smb + (kt % 3) * STAGE_BYTES;
        const uint32_t aoffA = Au + (wrow + lrow) * (AH_LD * 2) + lcol;
        const uint32_t aoffB = Au + BOFF + (wcol + lrow) * (AH_LD * 2) + lcol;

#pragma unroll
        for (int kc = 0; kc < 4; kc++) {
            uint32_t a0[4], a1[4];
            ldsm4(aoffA + kc * 32, a0[0], a0[1], a0[2], a0[3]);
            ldsm4(aoffA + 16 * (AH_LD * 2) + kc * 32, a1[0], a1[1], a1[2], a1[3]);
#pragma unroll
            for (int jj = 0; jj < 4; jj++) {
                uint32_t b[4];
                ldsm4(aoffB + jj * 16 * (AH_LD * 2) + kc * 32, b[0], b[1], b[2], b[3]);
                mma_f16(acc[0][jj * 2],     a0, b[0], b[2], acc[0][jj * 2]);
                mma_f16(acc[0][jj * 2 + 1], a0, b[1], b[3], acc[0][jj * 2 + 1]);
                mma_f16(acc[1][jj * 2],     a1, b[0], b[2], acc[1][jj * 2]);
                mma_f16(acc[1][jj * 2 + 1], a1, b[1], b[3], acc[1][jj * 2 + 1]);
            }
        }
    }

    __syncthreads();
    __half* Csh = reinterpret_cast<__half*>(smc);
#pragma unroll
    for (int i = 0; i < 2; i++)
#pragma unroll
        for (int n8 = 0; n8 < 8; n8++) {
            const int row = wrow + i * 16 + gr;
            const int col = wcol + n8 * 8 + 2 * tg;
            const float b0 = sbias[col], b1 = sbias[col + 1];
            *reinterpret_cast<uint32_t*>(Csh + row * CH_LD + col) =
                packh2((acc[i][n8][0] + b0) * qscale, (acc[i][n8][1] + b1) * qscale);
            *reinterpret_cast<uint32_t*>(Csh + (row + 8) * CH_LD + col) =
                packh2((acc[i][n8][2] + b0) * qscale, (acc[i][n8][3] + b1) * qscale);
        }
    __syncthreads();

    const int bb = m0 >> 11;
#pragma unroll
    for (int i = 0; i < 8; i++) {
        const int f = tid + i * 256;       // 0..2047, 8-half chunks
        const int r = f >> 4;
        const int c8 = (f & 15) * 8;
        const int t = (m0 & (TT - 1)) + r;
        const int n = nloc + c8;
        const int h = n >> 6, d = n & 63;
        uint4 v = *reinterpret_cast<const uint4*>(Csh + r * CH_LD + c8);
        *reinterpret_cast<uint4*>(dst + ((size_t)((bb * HH + h) * TT + t)) * DD + d) = v;
    }
}

// ---------------------------------------------------------------------------
// Kernel 3: output projection, fp16 MMA. grid (8, 32). fp32 out + gated bias.
// ---------------------------------------------------------------------------
__global__ __launch_bounds__(256, 2) void out_gemm_h(
    const float* __restrict__ bo, const float* __restrict__ gate,
    float* __restrict__ out)
{
    extern __shared__ char smc[];
    const uint32_t smb = smem_u32(smc);
    __shared__ float gbias[128];

    const int n0 = blockIdx.x * 128;
    const int m0 = blockIdx.y * 128;

    const int tid  = threadIdx.x;
    const int wid  = tid >> 5;
    const int lane = tid & 31;
    const int gr   = lane >> 2;
    const int tg   = lane & 3;
    const int wrow = (wid & 3) * 32;
    const int wcol = (wid >> 2) * 64;
    const int lrow = lane & 15;
    const int lcol = (lane >> 4) * 16;

    if (tid < 128) {
        float s = 0.f;
#pragma unroll
        for (int hh = 0; hh < HH; hh++)
            s = fmaf(gate[hh], bo[(size_t)hh * EE + n0 + tid], s);
        gbias[tid] = s;
    }

    auto issue = [&](int kt) {
        const int k0 = kt * 64;
        const uint32_t Au = smb + (kt % 3) * STAGE_BYTES;
        const uint32_t Bu = Au + BOFF;
#pragma unroll
        for (int i = 0; i < 4; i++) {
            const int ch = tid + i * 256;
            const int r = ch >> 3, c = ch & 7;
            cp16(Au + r * (AH_LD * 2) + c * 16, g_attnh + (size_t)(m0 + r) * EE + k0 + c * 8);
        }
#pragma unroll
        for (int i = 0; i < 4; i++) {
            const int ch = tid + i * 256;
            const int r = ch >> 3, c = ch & 7;
            cp16(Bu + r * (AH_LD * 2) + c * 16, g_Woth + (size_t)(n0 + r) * EE + k0 + c * 8);
        }
        cp_commit();
    };

    float acc[2][8][4];
#pragma unroll
    for (int i = 0; i < 2; i++)
#pragma unroll
        for (int j = 0; j < 8; j++)
#pragma unroll
            for (int k = 0; k < 4; k++) acc[i][j][k] = 0.f;

    issue(0);
    issue(1);

    for (int kt = 0; kt < 16; kt++) {
        if (kt == 15) cp_wait0(); else cp_wait1();
        __syncthreads();
        if (kt + 2 < 16) issue(kt + 2);

        const uint32_t Au = smb + (kt % 3) * STAGE_BYTES;
        const uint32_t aoffA = Au + (wrow + lrow) * (AH_LD * 2) + lcol;
        const uint32_t aoffB = Au + BOFF + (wcol + lrow) * (AH_LD * 2) + lcol;

#pragma unroll
        for (int kc = 0; kc < 4; kc++) {
            uint32_t a0[4], a1[4];
            ldsm4(aoffA + kc * 32, a0[0], a0[1], a0[2], a0[3]);
            ldsm4(aoffA + 16 * (AH_LD * 2) + kc * 32, a1[0], a1[1], a1[2], a1[3]);
#pragma unroll
            for (int jj = 0; jj < 4; jj++) {
                uint32_t b[4];
                ldsm4(aoffB + jj * 16 * (AH_LD * 2) + kc * 32, b[0], b[1], b[2], b[3]);
                mma_f16(acc[0][jj * 2],     a0, b[0], b[2], acc[0][jj * 2]);
                mma_f16(acc[0][jj * 2 + 1], a0, b[1], b[3], acc[0][jj * 2 + 1]);
                mma_f16(acc[1][jj * 2],     a1, b[0], b[2], acc[1][jj * 2]);
                mma_f16(acc[1][jj * 2 + 1], a1, b[1], b[3], acc[1][jj * 2 + 1]);
            }
        }
    }

    __syncthreads();
    float* Cs = reinterpret_cast<float*>(smc);
#pragma unroll
    for (int i = 0; i < 2; i++)
#pragma unroll
        for (int n8 = 0; n8 < 8; n8++) {
            const int row = wrow + i * 16 + gr;
            const int col = wcol + n8 * 8 + 2 * tg;
            *reinterpret_cast<float2*>(Cs + row * CF_LD + col) =
                make_float2(acc[i][n8][0], acc[i][n8][1]);
            *reinterpret_cast<float2*>(Cs + (row + 8) * CF_LD + col) =
                make_float2(acc[i][n8][2], acc[i][n8][3]);
        }
    __syncthreads();

#pragma unroll
    for (int i = 0; i < 16; i++) {
        const int f = tid + i * 256;
        const int r = f >> 5;
        const int c4 = (f & 31) * 4;
        float4 v = *reinterpret_cast<const float4*>(Cs + r * CF_LD + c4);
        v.x += gbias[c4 + 0];
        v.y += gbias[c4 + 1];
        v.z += gbias[c4 + 2];
        v.w += gbias[c4 + 3];
        *reinterpret_cast<float4*>(out + (size_t)(m0 + r) * EE + n0 + c4) = v;
    }
}

// ---------------------------------------------------------------------------
// Kernel 2: FA2 flash attention, fp16 MMA. CTA = 128 queries x bh.
// 256 threads / 8 warps, 16 q-rows each. P in fp16 via h2exp2; row-sums via
// ones-column MMA. 4-stage cp.async K/V pipeline (audited in-bounds).
// ---------------------------------------------------------------------------
#define KH_LD 72
#define KTILE_BYTES (64 * KH_LD * 2)   // 9216
#define ATTN_STAGE (2 * KTILE_BYTES)   // 18432
#define QTILE_BYTES (128 * KH_LD * 2)  // 18432
#define ATTN_SMEM (QTILE_BYTES + 4 * ATTN_STAGE)  // 92160

__global__ __launch_bounds__(256, 2) void flash_attn_h(const float* __restrict__ gate)
{
    extern __shared__ char smc[];
    const uint32_t smb = smem_u32(smc);
    const uint32_t Qu  = smb;
    const uint32_t St0 = smb + QTILE_BYTES;

    const int bh = blockIdx.y;
    const int q0 = blockIdx.x * 128;
    const int tid  = threadIdx.x;
    const int wid  = tid >> 5;
    const int lane = tid & 31;
    const int gr   = lane >> 2;
    const int tg   = lane & 3;
    const int wrow = wid * 16;
    const int lrow = lane & 15;
    const int lcol = (lane >> 4) * 16;

    const __half* Qg = g_Qh + ((size_t)bh * TT + q0) * DD;
    const __half* Kg = g_Kh + (size_t)bh * TT * DD;
    const __half* Vg = g_Vh + (size_t)bh * TT * DD;

    auto issueKV = [&](int kb) {
        const uint32_t Ku = St0 + (kb & 3) * ATTN_STAGE;
        const uint32_t Vu = Ku + KTILE_BYTES;
        const __half* Ksrc = Kg + (size_t)(kb * 64) * DD;
        const __half* Vsrc = Vg + (size_t)(kb * 64) * DD;
#pragma unroll
        for (int i = 0; i < 2; i++) {
            const int ch = tid + i * 256;     // 0..511
            const int r = ch >> 3, c = ch & 7;
            cp16(Ku + r * (KH_LD * 2) + c * 16, Ksrc + (size_t)r * DD + c * 8);
        }
#pragma unroll
        for (int i = 0; i < 2; i++) {
            const int ch = tid + i * 256;
            const int r = ch >> 3, c = ch & 7;
            cp16(Vu + r * (KH_LD * 2) + c * 16, Vsrc + (size_t)r * DD + c * 8);
        }
        cp_commit();
    };

    // Group 0 = Q tile + K/V tile 0; then KV1, KV2 (3 groups in flight)
    {
#pragma unroll
        for (int i = 0; i < 4; i++) {
            const int ch = tid + i * 256;     // 0..1023
            const int r = ch >> 3, c = ch & 7;
            cp16(Qu + r * (KH_LD * 2) + c * 16, Qg + (size_t)r * DD + c * 8);
        }
        issueKV(0);   // commits group 0 (Q + KV0)
    }
    issueKV(1);
    issueKV(2);

    cp_wait2();       // Q + KV0 complete
    __syncthreads();

    // Q A-fragments: 4 k-chunks (d 0..63)
    uint32_t qa[4][4];
    {
        const uint32_t qoff = Qu + (wrow + lrow) * (KH_LD * 2) + lcol;
#pragma unroll
        for (int kc = 0; kc < 4; kc++)
            ldsm4(qoff + kc * 32, qa[kc][0], qa[kc][1], qa[kc][2], qa[kc][3]);
    }

    float oc[8][4];
    float lc[4];      // ones-column accumulator: lc[0]=row gr sum, lc[2]=row gr+8
#pragma unroll
    for (int j = 0; j < 8; j++)
#pragma unroll
        for (int k = 0; k < 4; k++) oc[j][k] = 0.f;
#pragma unroll
    for (int k = 0; k < 4; k++) lc[k] = 0.f;
    float m0 = -1e30f, m1 = -1e30f;

    const int NKB = TT / 64;   // 32
    for (int kb = 0; kb < NKB; kb++) {
        if (kb == NKB - 1) cp_wait0();
        else if (kb == NKB - 2) cp_wait1();
        else cp_wait2();
        __syncthreads();
        if (kb + 3 < NKB) issueKV(kb + 3);

        const uint32_t Ku = St0 + (kb & 3) * ATTN_STAGE;
        const uint32_t koff = Ku + lrow * (KH_LD * 2) + lcol;
        const uint32_t voff = Ku + KTILE_BYTES + lrow * (KH_LD * 2) + lcol;

        // ---- S = Q K^T (16 x 64 per warp), log2-domain scores ----
        float sc[8][4];
#pragma unroll
        for (int j = 0; j < 8; j++)
#pragma unroll
            for (int k = 0; k < 4; k++) sc[j][k] = 0.f;

#pragma unroll
        for (int kc = 0; kc < 4; kc++) {
#pragma unroll
            for (int jp = 0; jp < 4; jp++) {
                uint32_t b[4];
                ldsm4(koff + jp * 16 * (KH_LD * 2) + kc * 32, b[0], b[1], b[2], b[3]);
                mma_f16(sc[jp * 2],     qa[kc], b[0], b[2], sc[jp * 2]);
                mma_f16(sc[jp * 2 + 1], qa[kc], b[1], b[3], sc[jp * 2 + 1]);
            }
        }

        // ---- Online softmax (base-2): max via shuffles ----
        float mx0 = -1e30f, mx1 = -1e30f;
#pragma unroll
        for (int j = 0; j < 8; j++) {
            mx0 = fmaxf(mx0, fmaxf(sc[j][0], sc[j][1]));
            mx1 = fmaxf(mx1, fmaxf(sc[j][2], sc[j][3]));
        }
        mx0 = fmaxf(mx0, __shfl_xor_sync(0xffffffffu, mx0, 1));
        mx0 = fmaxf(mx0, __shfl_xor_sync(0xffffffffu, mx0, 2));
        mx1 = fmaxf(mx1, __shfl_xor_sync(0xffffffffu, mx1, 1));
        mx1 = fmaxf(mx1, __shfl_xor_sync(0xffffffffu, mx1, 2));

        const float mn0 = fmaxf(m0, mx0);
        const float mn1 = fmaxf(m1, mx1);
        float al0, al1;
        asm("ex2.approx.f32 %0, %1;" : "=f"(al0) : "f"(m0 - mn0));
        asm("ex2.approx.f32 %0, %1;" : "=f"(al1) : "f"(m1 - mn1));
        m0 = mn0;
        m1 = mn1;

        // Rescale O and l accumulators
#pragma unroll
        for (int j = 0; j < 8; j++) {
            oc[j][0] *= al0;
            oc[j][1] *= al0;
            oc[j][2] *= al1;
            oc[j][3] *= al1;
        }
        lc[0] *= al0; lc[1] *= al0; lc[2] *= al1; lc[3] *= al1;

        // ---- P = 2^(S - mn) directly in fp16 A-frag layout ----
        uint32_t pa[4][4];
#pragma unroll
        for (int kc = 0; kc < 4; kc++) {
            pa[kc][0] = exp2h2(sc[2 * kc][0] - mn0,     sc[2 * kc][1] - mn0);
            pa[kc][1] = exp2h2(sc[2 * kc][2] - mn1,     sc[2 * kc][3] - mn1);
            pa[kc][2] = exp2h2(sc[2 * kc + 1][0] - mn0, sc[2 * kc + 1][1] - mn0);
            pa[kc][3] = exp2h2(sc[2 * kc + 1][2] - mn1, sc[2 * kc + 1][3] - mn1);
        }

        // ---- O += P V ; l += P * ones (row-sum via MMA, no shuffles) ----
#pragma unroll
        for (int kc = 0; kc < 4; kc++) {
            mma_f16(lc, pa[kc], ONES_H2, ONES_H2, lc);
#pragma unroll
            for (int jp = 0; jp < 4; jp++) {
                uint32_t b[4];
                ldsm4t(voff + kc * 16 * (KH_LD * 2) + jp * 32, b[0], b[1], b[2], b[3]);
                mma_f16(oc[jp * 2],     pa[kc], b[0], b[1], oc[jp * 2]);
                mma_f16(oc[jp * 2 + 1], pa[kc], b[2], b[3], oc[jp * 2 + 1]);
            }
        }
    }

    // ---- Epilogue: normalize, apply gate, write fp16 g_attnh ----
    const int b  = bh >> 4;
    const int h  = bh & 15;
    const float g = gate[h];
    const float inv0 = g / lc[0];
    const float inv1 = g / lc[2];
    const int r0 = q0 + wrow + gr;
    __half* row0 = g_attnh + ((size_t)(b * TT + r0)) * EE + h * DD;
    __half* row1 = g_attnh + ((size_t)(b * TT + r0 + 8)) * EE + h * DD;
#pragma unroll
    for (int j = 0; j < 8; j++) {
        const int col = j * 8 + 2 * tg;
        *reinterpret_cast<uint32_t*>(row0 + col) = packh2(oc[j][0] * inv0, oc[j][1] * inv0);
        *reinterpret_cast<uint32_t*>(row1 + col) = packh2(oc[j][2] * inv1, oc[j][3] * inv1);
    }
}

// ---------------------------------------------------------------------------
extern "C" void kernel_launch(void* const* d_in, const int* in_sizes, int n_in,
                              void* d_out, int out_size)
{
    const float* X    = (const float*)d_in[0];
    const float* Wq   = (const float*)d_in[1];
    const float* bq   = (const float*)d_in[2];
    const float* Wk   = (const float*)d_in[3];
    const float* bk   = (const float*)d_in[4];
    const float* Wv   = (const float*)d_in[5];
    const float* bv   = (const float*)d_in[6];
    const float* Wo   = (const float*)d_in[7];
    const float* bo   = (const float*)d_in[8];
    const float* gate = (const float*)d_in[9];
    float* out = (float*)d_out;

    __half* Xh;
    __half* Wth;
    __half* Woth;
    cudaGetSymbolAddress((void**)&Xh,   g_Xh);
    cudaGetSymbolAddress((void**)&Wth,  g_Wth);
    cudaGetSymbolAddress((void**)&Woth, g_Woth);

    cudaFuncSetAttribute(qkv_gemm_h,   cudaFuncAttributeMaxDynamicSharedMemorySize, GEMM_SMEM);
    cudaFuncSetAttribute(out_gemm_h,   cudaFuncAttributeMaxDynamicSharedMemorySize, GEMM_SMEM);
    cudaFuncSetAttribute(flash_attn_h, cudaFuncAttributeMaxDynamicSharedMemorySize, ATTN_SMEM);

    // 0) All conversions in one launch
    cvt_all<<<8192, 256>>>(X, Wq, Wk, Wv, Wo, Xh, Wth, Woth);

    // 1) QKV projection (fp16 MMA, 128x128 CTA tile, 3-stage, BK=64)
    qkv_gemm_h<<<dim3(3072 / 128, MM / 128), 256, GEMM_SMEM>>>(bq, bk, bv);
    // 2) Flash attention (fp16 MMA, 4-stage)
    flash_attn_h<<<dim3(TT / 128, BH), 256, ATTN_SMEM>>>(gate);
    // 3) Output projection (fp16 MMA, 128x128 CTA tile, 3-stage, BK=64)
    out_gemm_h<<<dim3(EE / 128, MM / 128), 256, GEMM_SMEM>>>(bo, gate, out);
}

// round 13
// speedup vs baseline: 1.0524x; 1.0061x over previous
#include <cuda_runtime.h>
#include <cuda_fp16.h>
#include <cstdint>
#include <math.h>

// ---------------------------------------------------------------------------
// Problem constants
// ---------------------------------------------------------------------------
#define BB 2
#define TT 2048
#define EE 1024
#define HH 16
#define DD 64
#define MM (BB * TT)
#define BH (BB * HH)

// 0.125 (1/sqrt(64)) * log2(e): folded into Q so softmax uses exp2
#define SCALE_Q 0.18033688011112042f
#define ONES_H2 0x3C003C00u

// Scratch (device globals; allocation-free)
__device__ __half g_Xh[MM * EE];            // hidden fp16 [m][e]
__device__ __half g_Wth[3 * EE * EE];       // [mat][n=h*64+d][e] fp16
__device__ __half g_Woth[EE * EE];          // [n=e][k=h*64+d] fp16
__device__ __half g_Qh[BH * TT * DD];       // [bh][t][d] (pre-scaled by SCALE_Q)
__device__ __half g_Kh[BH * TT * DD];       // [bh][t][d]
__device__ __half g_Vh[BH * TT * DD];       // [bh][t][d]
__device__ __half g_attnh[MM * EE];         // gated attn out fp16 [m][h*64+d]

// ---------------------------------------------------------------------------
// Helpers
// ---------------------------------------------------------------------------
__device__ __forceinline__ uint32_t smem_u32(const void* p) {
    return (uint32_t)__cvta_generic_to_shared(p);
}
__device__ __forceinline__ void cp16(uint32_t dst, const void* src) {
    asm volatile("cp.async.cg.shared.global [%0], [%1], 16;\n" :: "r"(dst), "l"(src));
}
__device__ __forceinline__ void cp_commit() {
    asm volatile("cp.async.commit_group;\n" ::: "memory");
}
__device__ __forceinline__ void cp_wait0() {
    asm volatile("cp.async.wait_group 0;\n" ::: "memory");
}
__device__ __forceinline__ void cp_wait1() {
    asm volatile("cp.async.wait_group 1;\n" ::: "memory");
}
__device__ __forceinline__ void cp_wait2() {
    asm volatile("cp.async.wait_group 2;\n" ::: "memory");
}
__device__ __forceinline__ void ldsm4(uint32_t addr, uint32_t& r0, uint32_t& r1,
                                      uint32_t& r2, uint32_t& r3) {
    asm volatile("ldmatrix.sync.aligned.m8n8.x4.shared.b16 {%0,%1,%2,%3}, [%4];"
                 : "=r"(r0), "=r"(r1), "=r"(r2), "=r"(r3) : "r"(addr));
}
__device__ __forceinline__ void ldsm4t(uint32_t addr, uint32_t& r0, uint32_t& r1,
                                       uint32_t& r2, uint32_t& r3) {
    asm volatile("ldmatrix.sync.aligned.m8n8.x4.trans.shared.b16 {%0,%1,%2,%3}, [%4];"
                 : "=r"(r0), "=r"(r1), "=r"(r2), "=r"(r3) : "r"(addr));
}
// m16n8k16 fp16 mma, fp32 accumulate
__device__ __forceinline__ void mma_f16(float* d, const uint32_t* a,
                                        uint32_t b0, uint32_t b1, const float* c) {
    asm volatile(
        "mma.sync.aligned.m16n8k16.row.col.f32.f16.f16.f32 "
        "{%0,%1,%2,%3}, {%4,%5,%6,%7}, {%8,%9}, {%10,%11,%12,%13};\n"
        : "=f"(d[0]), "=f"(d[1]), "=f"(d[2]), "=f"(d[3])
        : "r"(a[0]), "r"(a[1]), "r"(a[2]), "r"(a[3]),
          "r"(b0), "r"(b1),
          "f"(c[0]), "f"(c[1]), "f"(c[2]), "f"(c[3]));
}
__device__ __forceinline__ uint32_t packh2(float lo, float hi) {
    __half2 h = __floats2half2_rn(lo, hi);
    return *reinterpret_cast<uint32_t*>(&h);
}
// 2^x on a packed half2 built from two floats
__device__ __forceinline__ uint32_t exp2h2(float lo, float hi) {
    __half2 h = h2exp2(__floats2half2_rn(lo, hi));
    return *reinterpret_cast<uint32_t*>(&h);
}

// ---------------------------------------------------------------------------
// Kernel 0: ALL conversions, bandwidth-optimized. Grid = 2048 blocks:
//   [0, 1024)     : X fp32 -> fp16, 4 float4 per thread (MLP 4)
//   [1024, 1792)  : Wq/Wk/Wv -> transposed fp16, 64x64 tile per block
//   [1792, 2048)  : Wo -> transposed fp16, 64x64 tile per block
// ---------------------------------------------------------------------------
__global__ __launch_bounds__(256) void cvt_all(
    const float* __restrict__ X,
    const float* __restrict__ Wq, const float* __restrict__ Wk,
    const float* __restrict__ Wv, const float* __restrict__ Wo,
    __half* __restrict__ Xh, __half* __restrict__ Wth,
    __half* __restrict__ Woth)
{
    const int bid = blockIdx.x;
    const int tid = threadIdx.x;

    if (bid < 1024) {
        // X: 1M float4 total; 4 per thread, batched for MLP
        float4 v[4];
#pragma unroll
        for (int i = 0; i < 4; i++) {
            const int f = bid * 1024 + tid + i * 256;
            v[i] = *reinterpret_cast<const float4*>(X + (size_t)f * 4);
        }
#pragma unroll
        for (int i = 0; i < 4; i++) {
            const int f = bid * 1024 + tid + i * 256;
            uint2 o;
            o.x = packh2(v[i].x, v[i].y);
            o.y = packh2(v[i].z, v[i].w);
            *reinterpret_cast<uint2*>(Xh + (size_t)f * 4) = o;
        }
        return;
    }

    // 64x64 transpose tile, 256 threads, 16 elems/thread
    __shared__ float tile[64][65];
    const int tx = tid & 63;         // column within tile (load) / row (store)
    const int ty = tid >> 6;         // 0..3

    const float* src;
    __half* dst;
    int srcC, dstC;      // source row length, dest row length
    int r0, c0;          // tile origin in source coords (r0 = row, c0 = col)

    if (bid < 1792) {
        // QKV weights: per (mat, h): src [E][D] -> dst [D][E]
        const int idx = bid - 1024;   // 0..767
        const int z   = idx >> 4;     // 0..47
        const int mat = z >> 4;
        const int h   = z & 15;
        r0 = (idx & 15) * 64;         // E tile
        c0 = 0;                       // D = 64 = one tile
        src = (mat == 0 ? Wq : (mat == 1 ? Wk : Wv)) + (size_t)h * EE * DD;
        dst = Wth + (size_t)mat * EE * EE + (size_t)h * DD * EE;
        srcC = DD;
        dstC = EE;
    } else {
        // Wo: src [H*D=1024][E=1024] -> dst [E][H*D]
        const int idx = bid - 1792;   // 0..255
        r0 = (idx >> 4) * 64;
        c0 = (idx & 15) * 64;
        src = Wo;
        dst = Woth;
        srcC = EE;
        dstC = EE;
    }

    // Load 64 rows x 64 cols
#pragma unroll
    for (int i = 0; i < 16; i++) {
        const int r = ty + i * 4;
        tile[r][tx] = src[(size_t)(r0 + r) * srcC + c0 + tx];
    }
    __syncthreads();
    // Store transposed: dst[(c0 + c)][r0 + tx]
#pragma unroll
    for (int i = 0; i < 16; i++) {
        const int c = ty + i * 4;
        dst[(size_t)(c0 + c) * dstC + r0 + tx] = __float2half_rn(tile[tx][c]);
    }
}

// ---------------------------------------------------------------------------
// GEMM (R8 geometry): CTA tile 128x128, 8 warps, warp tile 32x64.
// BK = 64 halves -> 16 mainloop iterations. 3 stages of
// (A 128x72h, B 128x72h) = 36864 B/stage, 110592 total, 2 CTAs/SM.
// B-fragments software-prefetched one jj ahead inside each kc chunk.
// ---------------------------------------------------------------------------
#define AH_LD 72          // halves (144 B row)
#define STAGE_BYTES 36864
#define BOFF 18432
#define GEMM_SMEM (3 * STAGE_BYTES)
#define CH_LD 136         // halves (qkv epilogue)
#define CF_LD 132         // floats (out epilogue)

// ---------------------------------------------------------------------------
// Kernel 1: fused QKV projection, fp16 MMA. grid (24, 32).
// ---------------------------------------------------------------------------
__global__ __launch_bounds__(256, 2) void qkv_gemm_h(
    const float* __restrict__ bq, const float* __restrict__ bk,
    const float* __restrict__ bv)
{
    extern __shared__ char smc[];
    const uint32_t smb = smem_u32(smc);
    __shared__ float sbias[128];

    const int n0   = blockIdx.x * 128;
    const int m0   = blockIdx.y * 128;
    const int mat  = n0 >> 10;
    const int nloc = n0 & 1023;

    const __half* Wt  = g_Wth + (size_t)mat * EE * EE;
    const float* bias = (mat == 0 ? bq : (mat == 1 ? bk : bv));
    __half* dst       = (mat == 0 ? g_Qh : (mat == 1 ? g_Kh : g_Vh));
    const float qscale = (mat == 0) ? SCALE_Q : 1.0f;

    const int tid  = threadIdx.x;
    const int wid  = tid >> 5;
    const int lane = tid & 31;
    const int gr   = lane >> 2;
    const int tg   = lane & 3;
    const int wrow = (wid & 3) * 32;
    const int wcol = (wid >> 2) * 64;
    const int lrow = lane & 15;
    const int lcol = (lane >> 4) * 16;   // byte offset

    if (tid < 128) sbias[tid] = bias[nloc + tid];

    auto issue = [&](int kt) {
        const int k0 = kt * 64;          // halves
        const uint32_t Au = smb + (kt % 3) * STAGE_BYTES;
        const uint32_t Bu = Au + BOFF;
#pragma unroll
        for (int i = 0; i < 4; i++) {
            const int ch = tid + i * 256;       // 0..1023
            const int r = ch >> 3, c = ch & 7;
            cp16(Au + r * (AH_LD * 2) + c * 16, g_Xh + (size_t)(m0 + r) * EE + k0 + c * 8);
        }
#pragma unroll
        for (int i = 0; i < 4; i++) {
            const int ch = tid + i * 256;
            const int r = ch >> 3, c = ch & 7;
            cp16(Bu + r * (AH_LD * 2) + c * 16, Wt + (size_t)(nloc + r) * EE + k0 + c * 8);
        }
        cp_commit();
    };

    float acc[2][8][4];
#pragma unroll
    for (int i = 0; i < 2; i++)
#pragma unroll
        for (int j = 0; j < 8; j++)
#pragma unroll
            for (int k = 0; k < 4; k++) acc[i][j][k] = 0.f;

    issue(0);
    issue(1);

    for (int kt = 0; kt < 16; kt++) {
        if (kt == 15) cp_wait0(); else cp_wait1();
        __syncthreads();
        if (kt + 2 < 16) issue(kt + 2);

        const uint32_t Au = smb + (kt % 3) * STAGE_BYTES;
        const uint32_t aoffA = Au + (wrow + lrow) * (AH_LD * 2) + lcol;
        const uint32_t aoffB = Au + BOFF + (wcol + lrow) * (AH_LD * 2) + lcol;

#pragma unroll
        for (int kc = 0; kc < 4; kc++) {
            uint32_t a0[4], a1[4];
            ldsm4(aoffA + kc * 32, a0[0], a0[1], a0[2], a0[3]);
            ldsm4(aoffA + 16 * (AH_LD * 2) + kc * 32, a1[0], a1[1], a1[2], a1[3]);
            uint32_t b[4];
            ldsm4(aoffB + kc * 32, b[0], b[1], b[2], b[3]);
#pragma unroll
            for (int jj = 0; jj < 4; jj++) {
                uint32_t bn[4];
                if (jj < 3)
                    ldsm4(aoffB + (jj + 1) * 16 * (AH_LD * 2) + kc * 32,
                          bn[0], bn[1], bn[2], bn[3]);
                mma_f16(acc[0][jj * 2],     a0, b[0], b[2], acc[0][jj * 2]);
                mma_f16(acc[0][jj * 2 + 1], a0, b[1], b[3], acc[0][jj * 2 + 1]);
                mma_f16(acc[1][jj * 2],     a1, b[0], b[2], acc[1][jj * 2]);
                mma_f16(acc[1][jj * 2 + 1], a1, b[1], b[3], acc[1][jj * 2 + 1]);
                if (jj < 3) {
                    b[0] = bn[0]; b[1] = bn[1]; b[2] = bn[2]; b[3] = bn[3];
                }
            }
        }
    }

    __syncthreads();
    __half* Csh = reinterpret_cast<__half*>(smc);
#pragma unroll
    for (int i = 0; i < 2; i++)
#pragma unroll
        for (int n8 = 0; n8 < 8; n8++) {
            const int row = wrow + i * 16 + gr;
            const int col = wcol + n8 * 8 + 2 * tg;
            const float b0 = sbias[col], b1 = sbias[col + 1];
            *reinterpret_cast<uint32_t*>(Csh + row * CH_LD + col) =
                packh2((acc[i][n8][0] + b0) * qscale, (acc[i][n8][1] + b1) * qscale);
            *reinterpret_cast<uint32_t*>(Csh + (row + 8) * CH_LD + col) =
                packh2((acc[i][n8][2] + b0) * qscale, (acc[i][n8][3] + b1) * qscale);
        }
    __syncthreads();

    const int bb = m0 >> 11;
#pragma unroll
    for (int i = 0; i < 8; i++) {
        const int f = tid + i * 256;       // 0..2047, 8-half chunks
        const int r = f >> 4;
        const int c8 = (f & 15) * 8;
        const int t = (m0 & (TT - 1)) + r;
        const int n = nloc + c8;
        const int h = n >> 6, d = n & 63;
        uint4 v = *reinterpret_cast<const uint4*>(Csh + r * CH_LD + c8);
        *reinterpret_cast<uint4*>(dst + ((size_t)((bb * HH + h) * TT + t)) * DD + d) = v;
    }
}

// ---------------------------------------------------------------------------
// Kernel 3: output projection, fp16 MMA. grid (8, 32). fp32 out + gated bias.
// ---------------------------------------------------------------------------
__global__ __launch_bounds__(256, 2) void out_gemm_h(
    const float* __restrict__ bo, const float* __restrict__ gate,
    float* __restrict__ out)
{
    extern __shared__ char smc[];
    const uint32_t smb = smem_u32(smc);
    __shared__ float gbias[128];

    const int n0 = blockIdx.x * 128;
    const int m0 = blockIdx.y * 128;

    const int tid  = threadIdx.x;
    const int wid  = tid >> 5;
    const int lane = tid & 31;
    const int gr   = lane >> 2;
    const int tg   = lane & 3;
    const int wrow = (wid & 3) * 32;
    const int wcol = (wid >> 2) * 64;
    const int lrow = lane & 15;
    const int lcol = (lane >> 4) * 16;

    if (tid < 128) {
        float s = 0.f;
#pragma unroll
        for (int hh = 0; hh < HH; hh++)
            s = fmaf(gate[hh], bo[(size_t)hh * EE + n0 + tid], s);
        gbias[tid] = s;
    }

    auto issue = [&](int kt) {
        const int k0 = kt * 64;
        const uint32_t Au = smb + (kt % 3) * STAGE_BYTES;
        const uint32_t Bu = Au + BOFF;
#pragma unroll
        for (int i = 0; i < 4; i++) {
            const int ch = tid + i * 256;
            const int r = ch >> 3, c = ch & 7;
            cp16(Au + r * (AH_LD * 2) + c * 16, g_attnh + (size_t)(m0 + r) * EE + k0 + c * 8);
        }
#pragma unroll
        for (int i = 0; i < 4; i++) {
            const int ch = tid + i * 256;
            const int r = ch >> 3, c = ch & 7;
            cp16(Bu + r * (AH_LD * 2) + c * 16, g_Woth + (size_t)(n0 + r) * EE + k0 + c * 8);
        }
        cp_commit();
    };

    float acc[2][8][4];
#pragma unroll
    for (int i = 0; i < 2; i++)
#pragma unroll
        for (int j = 0; j < 8; j++)
#pragma unroll
            for (int k = 0; k < 4; k++) acc[i][j][k] = 0.f;

    issue(0);
    issue(1);

    for (int kt = 0; kt < 16; kt++) {
        if (kt == 15) cp_wait0(); else cp_wait1();
        __syncthreads();
        if (kt + 2 < 16) issue(kt + 2);

        const uint32_t Au = smb + (kt % 3) * STAGE_BYTES;
        const uint32_t aoffA = Au + (wrow + lrow) * (AH_LD * 2) + lcol;
        const uint32_t aoffB = Au + BOFF + (wcol + lrow) * (AH_LD * 2) + lcol;

#pragma unroll
        for (int kc = 0; kc < 4; kc++) {
            uint32_t a0[4], a1[4];
            ldsm4(aoffA + kc * 32, a0[0], a0[1], a0[2], a0[3]);
            ldsm4(aoffA + 16 * (AH_LD * 2) + kc * 32, a1[0], a1[1], a1[2], a1[3]);
            uint32_t b[4];
            ldsm4(aoffB + kc * 32, b[0], b[1], b[2], b[3]);
#pragma unroll
            for (int jj = 0; jj < 4; jj++) {
                uint32_t bn[4];
                if (jj < 3)
                    ldsm4(aoffB + (jj + 1) * 16 * (AH_LD * 2) + kc * 32,
                          bn[0], bn[1], bn[2], bn[3]);
                mma_f16(acc[0][jj * 2],     a0, b[0], b[2], acc[0][jj * 2]);
                mma_f16(acc[0][jj * 2 + 1], a0, b[1], b[3], acc[0][jj * 2 + 1]);
                mma_f16(acc[1][jj * 2],     a1, b[0], b[2], acc[1][jj * 2]);
                mma_f16(acc[1][jj * 2 + 1], a1, b[1], b[3], acc[1][jj * 2 + 1]);
                if (jj < 3) {
                    b[0] = bn[0]; b[1] = bn[1]; b[2] = bn[2]; b[3] = bn[3];
                }
            }
        }
    }

    __syncthreads();
    float* Cs = reinterpret_cast<float*>(smc);
#pragma unroll
    for (int i = 0; i < 2; i++)
#pragma unroll
        for (int n8 = 0; n8 < 8; n8++) {
            const int row = wrow + i * 16 + gr;
            const int col = wcol + n8 * 8 + 2 * tg;
            *reinterpret_cast<float2*>(Cs + row * CF_LD + col) =
                make_float2(acc[i][n8][0], acc[i][n8][1]);
            *reinterpret_cast<float2*>(Cs + (row + 8) * CF_LD + col) =
                make_float2(acc[i][n8][2], acc[i][n8][3]);
        }
    __syncthreads();

#pragma unroll
    for (int i = 0; i < 16; i++) {
        const int f = tid + i * 256;
        const int r = f >> 5;
        const int c4 = (f & 31) * 4;
        float4 v = *reinterpret_cast<const float4*>(Cs + r * CF_LD + c4);
        v.x += gbias[c4 + 0];
        v.y += gbias[c4 + 1];
        v.z += gbias[c4 + 2];
        v.w += gbias[c4 + 3];
        *reinterpret_cast<float4*>(out + (size_t)(m0 + r) * EE + n0 + c4) = v;
    }
}

// ---------------------------------------------------------------------------
// Kernel 2: FA2 flash attention, fp16 MMA (unchanged from R12, 4-stage).
// ---------------------------------------------------------------------------
#define KH_LD 72
#define KTILE_BYTES (64 * KH_LD * 2)   // 9216
#define ATTN_STAGE (2 * KTILE_BYTES)   // 18432
#define QTILE_BYTES (128 * KH_LD * 2)  // 18432
#define ATTN_SMEM (QTILE_BYTES + 4 * ATTN_STAGE)  // 92160

__global__ __launch_bounds__(256, 2) void flash_attn_h(const float* __restrict__ gate)
{
    extern __shared__ char smc[];
    const uint32_t smb = smem_u32(smc);
    const uint32_t Qu  = smb;
    const uint32_t St0 = smb + QTILE_BYTES;

    const int bh = blockIdx.y;
    const int q0 = blockIdx.x * 128;
    const int tid  = threadIdx.x;
    const int wid  = tid >> 5;
    const int lane = tid & 31;
    const int gr   = lane >> 2;
    const int tg   = lane & 3;
    const int wrow = wid * 16;
    const int lrow = lane & 15;
    const int lcol = (lane >> 4) * 16;

    const __half* Qg = g_Qh + ((size_t)bh * TT + q0) * DD;
    const __half* Kg = g_Kh + (size_t)bh * TT * DD;
    const __half* Vg = g_Vh + (size_t)bh * TT * DD;

    auto issueKV = [&](int kb) {
        const uint32_t Ku = St0 + (kb & 3) * ATTN_STAGE;
        const uint32_t Vu = Ku + KTILE_BYTES;
        const __half* Ksrc = Kg + (size_t)(kb * 64) * DD;
        const __half* Vsrc = Vg + (size_t)(kb * 64) * DD;
#pragma unroll
        for (int i = 0; i < 2; i++) {
            const int ch = tid + i * 256;     // 0..511
            const int r = ch >> 3, c = ch & 7;
            cp16(Ku + r * (KH_LD * 2) + c * 16, Ksrc + (size_t)r * DD + c * 8);
        }
#pragma unroll
        for (int i = 0; i < 2; i++) {
            const int ch = tid + i * 256;
            const int r = ch >> 3, c = ch & 7;
            cp16(Vu + r * (KH_LD * 2) + c * 16, Vsrc + (size_t)r * DD + c * 8);
        }
        cp_commit();
    };

    // Group 0 = Q tile + K/V tile 0; then KV1, KV2 (3 groups in flight)
    {
#pragma unroll
        for (int i = 0; i < 4; i++) {
            const int ch = tid + i * 256;     // 0..1023
            const int r = ch >> 3, c = ch & 7;
            cp16(Qu + r * (KH_LD * 2) + c * 16, Qg + (size_t)r * DD + c * 8);
        }
        issueKV(0);   // commits group 0 (Q + KV0)
    }
    issueKV(1);
    issueKV(2);

    cp_wait2();       // Q + KV0 complete
    __syncthreads();

    // Q A-fragments: 4 k-chunks (d 0..63)
    uint32_t qa[4][4];
    {
        const uint32_t qoff = Qu + (wrow + lrow) * (KH_LD * 2) + lcol;
#pragma unroll
        for (int kc = 0; kc < 4; kc++)
            ldsm4(qoff + kc * 32, qa[kc][0], qa[kc][1], qa[kc][2], qa[kc][3]);
    }

    float oc[8][4];
    float lc[4];      // ones-column accumulator: lc[0]=row gr sum, lc[2]=row gr+8
#pragma unroll
    for (int j = 0; j < 8; j++)
#pragma unroll
        for (int k = 0; k < 4; k++) oc[j][k] = 0.f;
#pragma unroll
    for (int k = 0; k < 4; k++) lc[k] = 0.f;
    float m0 = -1e30f, m1 = -1e30f;

    const int NKB = TT / 64;   // 32
    for (int kb = 0; kb < NKB; kb++) {
        if (kb == NKB - 1) cp_wait0();
        else if (kb == NKB - 2) cp_wait1();
        else cp_wait2();
        __syncthreads();
        if (kb + 3 < NKB) issueKV(kb + 3);

        const uint32_t Ku = St0 + (kb & 3) * ATTN_STAGE;
        const uint32_t koff = Ku + lrow * (KH_LD * 2) + lcol;
        const uint32_t voff = Ku + KTILE_BYTES + lrow * (KH_LD * 2) + lcol;

        // ---- S = Q K^T (16 x 64 per warp), log2-domain scores ----
        float sc[8][4];
#pragma unroll
        for (int j = 0; j < 8; j++)
#pragma unroll
            for (int k = 0; k < 4; k++) sc[j][k] = 0.f;

#pragma unroll
        for (int kc = 0; kc < 4; kc++) {
#pragma unroll
            for (int jp = 0; jp < 4; jp++) {
                uint32_t b[4];
                ldsm4(koff + jp * 16 * (KH_LD * 2) + kc * 32, b[0], b[1], b[2], b[3]);
                mma_f16(sc[jp * 2],     qa[kc], b[0], b[2], sc[jp * 2]);
                mma_f16(sc[jp * 2 + 1], qa[kc], b[1], b[3], sc[jp * 2 + 1]);
            }
        }

        // ---- Online softmax (base-2): max via shuffles ----
        float mx0 = -1e30f, mx1 = -1e30f;
#pragma unroll
        for (int j = 0; j < 8; j++) {
            mx0 = fmaxf(mx0, fmaxf(sc[j][0], sc[j][1]));
            mx1 = fmaxf(mx1, fmaxf(sc[j][2], sc[j][3]));
        }
        mx0 = fmaxf(mx0, __shfl_xor_sync(0xffffffffu, mx0, 1));
        mx0 = fmaxf(mx0, __shfl_xor_sync(0xffffffffu, mx0, 2));
        mx1 = fmaxf(mx1, __shfl_xor_sync(0xffffffffu, mx1, 1));
        mx1 = fmaxf(mx1, __shfl_xor_sync(0xffffffffu, mx1, 2));

        const float mn0 = fmaxf(m0, mx0);
        const float mn1 = fmaxf(m1, mx1);
        float al0, al1;
        asm("ex2.approx.f32 %0, %1;" : "=f"(al0) : "f"(m0 - mn0));
        asm("ex2.approx.f32 %0, %1;" : "=f"(al1) : "f"(m1 - mn1));
        m0 = mn0;
        m1 = mn1;

        // Rescale O and l accumulators
#pragma unroll
        for (int j = 0; j < 8; j++) {
            oc[j][0] *= al0;
            oc[j][1] *= al0;
            oc[j][2] *= al1;
            oc[j][3] *= al1;
        }
        lc[0] *= al0; lc[1] *= al0; lc[2] *= al1; lc[3] *= al1;

        // ---- P = 2^(S - mn) directly in fp16 A-frag layout ----
        uint32_t pa[4][4];
#pragma unroll
        for (int kc = 0; kc < 4; kc++) {
            pa[kc][0] = exp2h2(sc[2 * kc][0] - mn0,     sc[2 * kc][1] - mn0);
            pa[kc][1] = exp2h2(sc[2 * kc][2] - mn1,     sc[2 * kc][3] - mn1);
            pa[kc][2] = exp2h2(sc[2 * kc + 1][0] - mn0, sc[2 * kc + 1][1] - mn0);
            pa[kc][3] = exp2h2(sc[2 * kc + 1][2] - mn1, sc[2 * kc + 1][3] - mn1);
        }

        // ---- O += P V ; l += P * ones (row-sum via MMA, no shuffles) ----
#pragma unroll
        for (int kc = 0; kc < 4; kc++) {
            mma_f16(lc, pa[kc], ONES_H2, ONES_H2, lc);
#pragma unroll
            for (int jp = 0; jp < 4; jp++) {
                uint32_t b[4];
                ldsm4t(voff + kc * 16 * (KH_LD * 2) + jp * 32, b[0], b[1], b[2], b[3]);
                mma_f16(oc[jp * 2],     pa[kc], b[0], b[1], oc[jp * 2]);
                mma_f16(oc[jp * 2 + 1], pa[kc], b[2], b[3], oc[jp * 2 + 1]);
            }
        }
    }

    // ---- Epilogue: normalize, apply gate, write fp16 g_attnh ----
    const int b  = bh >> 4;
    const int h  = bh & 15;
    const float g = gate[h];
    const float inv0 = g / lc[0];
    const float inv1 = g / lc[2];
    const int r0 = q0 + wrow + gr;
    __half* row0 = g_attnh + ((size_t)(b * TT + r0)) * EE + h * DD;
    __half* row1 = g_attnh + ((size_t)(b * TT + r0 + 8)) * EE + h * DD;
#pragma unroll
    for (int j = 0; j < 8; j++) {
        const int col = j * 8 + 2 * tg;
        *reinterpret_cast<uint32_t*>(row0 + col) = packh2(oc[j][0] * inv0, oc[j][1] * inv0);
        *reinterpret_cast<uint32_t*>(row1 + col) = packh2(oc[j][2] * inv1, oc[j][3] * inv1);
    }
}

// ---------------------------------------------------------------------------
extern "C" void kernel_launch(void* const* d_in, const int* in_sizes, int n_in,
                              void* d_out, int out_size)
{
    const float* X    = (const float*)d_in[0];
    const float* Wq   = (const float*)d_in[1];
    const float* bq   = (const float*)d_in[2];
    const float* Wk   = (const float*)d_in[3];
    const float* bk   = (const float*)d_in[4];
    const float* Wv   = (const float*)d_in[5];
    const float* bv   = (const float*)d_in[6];
    const float* Wo   = (const float*)d_in[7];
    const float* bo   = (const float*)d_in[8];
    const float* gate = (const float*)d_in[9];
    float* out = (float*)d_out;

    __half* Xh;
    __half* Wth;
    __half* Woth;
    cudaGetSymbolAddress((void**)&Xh,   g_Xh);
    cudaGetSymbolAddress((void**)&Wth,  g_Wth);
    cudaGetSymbolAddress((void**)&Woth, g_Woth);

    cudaFuncSetAttribute(qkv_gemm_h,   cudaFuncAttributeMaxDynamicSharedMemorySize, GEMM_SMEM);
    cudaFuncSetAttribute(out_gemm_h,   cudaFuncAttributeMaxDynamicSharedMemorySize, GEMM_SMEM);
    cudaFuncSetAttribute(flash_attn_h, cudaFuncAttributeMaxDynamicSharedMemorySize, ATTN_SMEM);

    // 0) All conversions in one bandwidth-optimized launch
    cvt_all<<<2048, 256>>>(X, Wq, Wk, Wv, Wo, Xh, Wth, Woth);

    // 1) QKV projection (fp16 MMA, 128x128 CTA tile, 3-stage, BK=64)
    qkv_gemm_h<<<dim3(3072 / 128, MM / 128), 256, GEMM_SMEM>>>(bq, bk, bv);
    // 2) Flash attention (fp16 MMA, 4-stage)
    flash_attn_h<<<dim3(TT / 128, BH), 256, ATTN_SMEM>>>(gate);
    // 3) Output projection (fp16 MMA, 128x128 CTA tile, 3-stage, BK=64)
    out_gemm_h<<<dim3(EE / 128, MM / 128), 256, GEMM_SMEM>>>(bo, gate, out);
}